// round 11
// baseline (speedup 1.0000x reference)
#include <cuda_runtime.h>

#define Bn 16
#define Qn 64
#define Kn 1024
#define Dn 256
#define Hn 128

// Scratch (device globals: no allocation allowed).
// Zero-initialized at module load; dead splits (k0 >= vlen[b]) are never
// written (vlen constant across replays), so they contribute exact zeros.
__device__ float g_qp[Bn*Qn*Hn];       // projected queries  [B,Q,H]
__device__ float g_kp[Bn*Kn*Hn];       // projected keys     [B,K,H]
__device__ float g_attn[Bn*Qn*Kn];     // exp(score) (no max shift; |score|<~15) [B,Q,K]
#define KS 16
#define OKS (Kn/KS)                    // 64 k per split
__device__ float g_part[KS*Bn*Qn*Dn];  // output partials [KS][B,Q,D]
__device__ float g_psum[KS*Bn*Qn];     // per-split exp row sums [KS][B*Q]

// ---------- packed f32x2 helpers (Blackwell) ----------
__device__ __forceinline__ unsigned long long pack2(float x, float y){
    unsigned long long r; asm("mov.b64 %0, {%1,%2};" : "=l"(r) : "f"(x), "f"(y)); return r;
}
__device__ __forceinline__ unsigned long long fma2(unsigned long long a, unsigned long long b, unsigned long long c){
    unsigned long long d; asm("fma.rn.f32x2 %0, %1, %2, %3;" : "=l"(d) : "l"(a), "l"(b), "l"(c)); return d;
}
__device__ __forceinline__ void unpack2(unsigned long long v, float& lo, float& hi){
    asm("mov.b64 {%0,%1}, %2;" : "=f"(lo), "=f"(hi) : "l"(v));
}

// ---------------- projection (q and k fused; dead k-rows skipped) ----------------
#define PR 32    // rows per block
#define PT 128   // threads (= Hn)
#define XS 36    // padded smem row stride (floats); 144B, 16B-aligned
#define QBLOCKS ((Bn*Qn)/PR)   // 32
#define KBLOCKS ((Bn*Kn)/PR)   // 512

__global__ __launch_bounds__(PT) void proj_kernel(const float* __restrict__ Xq,
                                                  const float* __restrict__ Wq,
                                                  const float* __restrict__ Xk,
                                                  const float* __restrict__ Wk,
                                                  const int* __restrict__ vlen){
    __shared__ float xs[Dn*XS];   // X tile transposed: xs[d][r]
    const float* X; const float* W; float* out; int row0;
    if (blockIdx.x < QBLOCKS){ X = Xq; W = Wq; out = g_qp; row0 = blockIdx.x * PR; }
    else {
        X = Xk; W = Wk; out = g_kp;
        row0 = (blockIdx.x - QBLOCKS) * PR;
        if ((row0 & (Kn-1)) >= vlen[row0 >> 10]) return;   // dead kp rows
    }
    const int t = threadIdx.x;

    for (int i = t; i < PR*Dn; i += PT){
        int r = i >> 8;          // /256
        int d = i & (Dn-1);
        xs[d*XS + r] = X[(row0 + r)*Dn + d];
    }
    __syncthreads();

    unsigned long long acc[PR/2];
#pragma unroll
    for (int i = 0; i < PR/2; i++) acc[i] = 0ull;

#pragma unroll 2
    for (int d = 0; d < Dn; d++){
        float w = W[d*Hn + t];                       // coalesced, L1-resident
        unsigned long long w2 = pack2(w, w);
        const ulonglong2* xp = reinterpret_cast<const ulonglong2*>(&xs[d*XS]);
#pragma unroll
        for (int m = 0; m < PR/4; m++){
            ulonglong2 xv = xp[m];                   // warp-uniform LDS.128 broadcast
            acc[2*m]   = fma2(w2, xv.x, acc[2*m]);
            acc[2*m+1] = fma2(w2, xv.y, acc[2*m+1]);
        }
    }
#pragma unroll
    for (int i = 0; i < PR/2; i++){
        float lo, hi; unpack2(acc[i], lo, hi);
        out[(row0 + 2*i    )*Hn + t] = lo;
        out[(row0 + 2*i + 1)*Hn + t] = hi;
    }
}

// --------- scores: writes exp(s), s = sum_h w_v[h]*tanh(qp+kp) ---------
// tanh via MUFU f16x2: one MUFU per 2 elements. Accumulation stays fp32.
// No max subtraction: |s| <= sum|w_v| ~ 9 -> exp in [1e-7, 1e4], exact in fp32.
#define SKT 32
#define SQT 16
#define ST  256

__global__ __launch_bounds__(ST) void score_kernel(const float* __restrict__ wv,
                                                   const int* __restrict__ vlen){
    const int b  = blockIdx.z;
    const int v  = vlen[b];
    const int k0 = blockIdx.x * SKT;
    if (k0 >= v) return;
    const int kmax = min(SKT, v - k0);

    __shared__ float ks[SKT*Hn];     // swizzled kp tile
    __shared__ float qs[SQT*Hn];     // q tile (plain)
    __shared__ float ws[Hn];
    const int t = threadIdx.x;
    if (t < Hn) ws[t] = wv[t];

    const float* kpb = g_kp + (size_t)(b*Kn + k0)*Hn;
    for (int i = t; i < SKT*Hn; i += ST){
        int j = i >> 7, h = i & 127;
        int sidx = j*Hn + ((((h>>2) ^ (j & 7))) << 2) + (h & 3);
        ks[sidx] = kpb[i];
    }
    const int q0 = blockIdx.y * SQT;
    const float* qpb = g_qp + (size_t)(b*Qn + q0)*Hn;
    for (int i = t; i < SQT*Hn; i += ST) qs[i] = qpb[i];
    __syncthreads();

    const int j  = t & 31;        // k lane
    const int qh = t >> 5;        // q phase 0..7 (uniform within warp)
    const int jx = j & 7;
    float* sc = g_attn + (size_t)(b*Qn + q0)*Kn;

#pragma unroll
    for (int qi = 0; qi < SQT/8; qi++){
        const int q = qi*8 + qh;
        float acc0 = 0.f, acc1 = 0.f;
#pragma unroll 8
        for (int c = 0; c < Hn/4; c++){
            float4 kv = *reinterpret_cast<const float4*>(&ks[j*Hn + ((c ^ jx) << 2)]);
            float4 qv = *reinterpret_cast<const float4*>(&qs[q*Hn + (c << 2)]); // broadcast
            float4 w4 = *reinterpret_cast<const float4*>(&ws[c << 2]);
            float ax = qv.x + kv.x, ay = qv.y + kv.y;
            float az = qv.z + kv.z, aw = qv.w + kv.w;
            unsigned p0, p1, t0, t1;
            asm("cvt.rn.f16x2.f32 %0, %1, %2;" : "=r"(p0) : "f"(ay), "f"(ax)); // hi=ay lo=ax
            asm("cvt.rn.f16x2.f32 %0, %1, %2;" : "=r"(p1) : "f"(aw), "f"(az));
            asm("tanh.approx.f16x2 %0, %1;" : "=r"(t0) : "r"(p0));
            asm("tanh.approx.f16x2 %0, %1;" : "=r"(t1) : "r"(p1));
            float f0, f1, f2, f3;
            asm("{ .reg .f16 l,h; mov.b32 {l,h}, %2; cvt.f32.f16 %0, l; cvt.f32.f16 %1, h; }"
                : "=f"(f0), "=f"(f1) : "r"(t0));
            asm("{ .reg .f16 l,h; mov.b32 {l,h}, %2; cvt.f32.f16 %0, l; cvt.f32.f16 %1, h; }"
                : "=f"(f2), "=f"(f3) : "r"(t1));
            acc0 += w4.x * f0;
            acc1 += w4.y * f1;
            acc0 += w4.z * f2;
            acc1 += w4.w * f3;
        }
        if (j < kmax) sc[q*Kn + k0 + j] = __expf(acc0 + acc1);
    }
}

// --------- out partials + per-split exp sums ---------
#define OQT 16
#define OT  256
#define ASTR 20   // padded attn-tile row stride (floats): 80B, 16B-aligned
#define VB 16     // V load batch

__global__ __launch_bounds__(OT, 4) void outpart_kernel(const float* __restrict__ V,
                                                        const int* __restrict__ vlen){
    const int qt = blockIdx.x;    // 0..3
    const int kz = blockIdx.y;    // 0..KS-1
    const int b  = blockIdx.z;
    const int v  = vlen[b];
    const int k0 = kz * OKS;
    if (k0 >= v) return;                      // dead split: stays zero
    const int q0 = qt * OQT;
    const int t  = threadIdx.x;
    const int kmax = min(OKS, v - k0);

    __shared__ float as[OKS*ASTR];   // e tile: as[k*ASTR + q]
    const float* attb = g_attn + (size_t)(b*Qn + q0)*Kn + k0;
    for (int i = t; i < OQT*OKS; i += OT){
        int q = i >> 6, k = i & (OKS-1);       // lanes: consecutive k, coalesced LDG
        as[k*ASTR + q] = (k < kmax) ? attb[q*Kn + k] : 0.f;
    }
    __syncthreads();

    const int d2 = t & 127;       // d-pair index
    const int qh = t >> 7;        // q-half (warp-uniform)
    const float2* Vt = reinterpret_cast<const float2*>(V + ((size_t)b*Kn + k0)*Dn) + d2;

    unsigned long long accA[4];   // (q2r,q2r+1) x d0 within this half
    unsigned long long accB[4];   // (q2r,q2r+1) x d1
#pragma unroll
    for (int r = 0; r < 4; r++){ accA[r] = 0ull; accB[r] = 0ull; }

#pragma unroll
    for (int gb = 0; gb < OKS/VB; gb++){
        float2 vb[VB];                             // front-batched: MLP=16
#pragma unroll
        for (int i = 0; i < VB; i++) vb[i] = Vt[(size_t)(gb*VB + i)*(Dn/2)];
#pragma unroll
        for (int i = 0; i < VB; i++){
            int k = gb*VB + i;
            unsigned long long v0 = pack2(vb[i].x, vb[i].x);
            unsigned long long v1 = pack2(vb[i].y, vb[i].y);
            const ulonglong2* ap = reinterpret_cast<const ulonglong2*>(&as[k*ASTR]) + 2*qh;
            ulonglong2 a0 = ap[0];    // q = qh*8 + 0..3, broadcast
            ulonglong2 a1 = ap[1];    // q = qh*8 + 4..7
            accA[0] = fma2(a0.x, v0, accA[0]);  accB[0] = fma2(a0.x, v1, accB[0]);
            accA[1] = fma2(a0.y, v0, accA[1]);  accB[1] = fma2(a0.y, v1, accB[1]);
            accA[2] = fma2(a1.x, v0, accA[2]);  accB[2] = fma2(a1.x, v1, accB[2]);
            accA[3] = fma2(a1.y, v0, accA[3]);  accB[3] = fma2(a1.y, v1, accB[3]);
        }
    }

    float* part = g_part + ((size_t)kz*Bn*Qn + b*Qn + q0 + qh*8)*Dn;
#pragma unroll
    for (int r = 0; r < 4; r++){
        float fa, fb, ga, gb2;
        unpack2(accA[r], fa, fb);
        unpack2(accB[r], ga, gb2);
        reinterpret_cast<float2*>(part + (2*r  )*Dn)[d2] = make_float2(fa, ga);
        reinterpret_cast<float2*>(part + (2*r+1)*Dn)[d2] = make_float2(fb, gb2);
    }

    // per-q exp sums of this split (smem unchanged since staging; no sync needed)
    if (t < OQT*8){
        int q = t >> 3, j = t & 7;
        float s = 0.f;
#pragma unroll
        for (int i = 0; i < 8; i++) s += as[(j*8 + i)*ASTR + q];
#pragma unroll
        for (int o = 4; o > 0; o >>= 1) s += __shfl_down_sync(0xffffffffu, s, o, 8);
        if (j == 0) g_psum[kz*(Bn*Qn) + b*Qn + q0 + q] = s;
    }
}

// ------- reduce: out = (1/sum psum) * sum part, all 16 splits unconditional -------
// 4 z per thread (low reg payload -> real MLP), 4 zq groups combined via smem.
#define RT 256
#define NOUT4 ((Bn*Qn*Dn)/4)   // 65536 float4
#define RI 64                  // i4 values per block

__global__ __launch_bounds__(RT) void reduce_kernel(float* __restrict__ out){
    const int t   = threadIdx.x;
    const int li  = t & (RI-1);
    const int zq  = t >> 6;                   // 0..3 (warp-uniform)
    const int i4  = blockIdx.x * RI + li;
    const int row = i4 >> 6;                  // (b,q) row: 64 float4 per row

    const float4* p = reinterpret_cast<const float4*>(g_part);
    float4 x[4];
    float  ps[4];
#pragma unroll
    for (int j = 0; j < 4; j++){              // 5 independent loads in flight
        int z = zq*4 + j;
        x[j]  = p[(size_t)z*NOUT4 + i4];
        ps[j] = g_psum[z*(Bn*Qn) + row];
    }
    x[0].x += x[1].x; x[0].y += x[1].y; x[0].z += x[1].z; x[0].w += x[1].w;
    x[2].x += x[3].x; x[2].y += x[3].y; x[2].z += x[3].z; x[2].w += x[3].w;
    x[0].x += x[2].x; x[0].y += x[2].y; x[0].z += x[2].z; x[0].w += x[2].w;
    ps[0] += ps[1]; ps[2] += ps[3]; ps[0] += ps[2];

    __shared__ float4 sx[3][RI];
    __shared__ float  sp[3][RI];
    if (zq){ sx[zq-1][li] = x[0]; sp[zq-1][li] = ps[0]; }
    __syncthreads();
    if (zq == 0){
        float4 s = x[0];
        float sm = ps[0];
#pragma unroll
        for (int g = 0; g < 3; g++){
            float4 o = sx[g][li];
            s.x += o.x; s.y += o.y; s.z += o.z; s.w += o.w;
            sm += sp[g][li];
        }
        const float inv = __fdividef(1.f, sm);
        s.x *= inv; s.y *= inv; s.z *= inv; s.w *= inv;
        reinterpret_cast<float4*>(out)[i4] = s;
    }
}

// ---------------- launch ----------------
extern "C" void kernel_launch(void* const* d_in, const int* in_sizes, int n_in,
                              void* d_out, int out_size){
    const float* queries = (const float*)d_in[0];
    const float* keys    = (const float*)d_in[1];
    const float* values  = (const float*)d_in[2];
    const int*   vlen    = (const int*)  d_in[3];
    const float* W_q     = (const float*)d_in[4];
    const float* W_k     = (const float*)d_in[5];
    const float* w_v     = (const float*)d_in[6];
    float* out = (float*)d_out;

    proj_kernel<<<QBLOCKS + KBLOCKS, PT>>>(queries, W_q, keys, W_k, vlen);  // 544 blocks
    score_kernel<<<dim3(Kn/SKT, Qn/SQT, Bn), ST>>>(w_v, vlen);              // 2048 blocks
    outpart_kernel<<<dim3(Qn/OQT, KS, Bn), OT>>>(values, vlen);             // 1024 blocks
    reduce_kernel<<<NOUT4/RI, RT>>>(out);                                   // 1024 blocks
}

// round 12
// speedup vs baseline: 1.0287x; 1.0287x over previous
#include <cuda_runtime.h>

#define Bn 16
#define Qn 64
#define Kn 1024
#define Dn 256
#define Hn 128

// Scratch (device globals: no allocation allowed).
// Zero-initialized at module load; dead splits (k0 >= vlen[b]) are never
// written (vlen constant across replays), so they contribute exact zeros.
__device__ float g_qp[Bn*Qn*Hn];       // projected queries  [B,Q,H]
__device__ float g_kp[Bn*Kn*Hn];       // projected keys     [B,K,H]
__device__ float g_attn[Bn*Qn*Kn];     // exp(score) (no max shift; |score|<~15) [B,Q,K]
#define KS 16
#define OKS (Kn/KS)                    // 64 k per split
__device__ float g_part[KS*Bn*Qn*Dn];  // output partials [KS][B,Q,D]
__device__ float g_psum[KS*Bn*Qn];     // per-split exp row sums [KS][B*Q]

// ---------- packed f32x2 helpers (Blackwell) ----------
__device__ __forceinline__ unsigned long long pack2(float x, float y){
    unsigned long long r; asm("mov.b64 %0, {%1,%2};" : "=l"(r) : "f"(x), "f"(y)); return r;
}
__device__ __forceinline__ unsigned long long fma2(unsigned long long a, unsigned long long b, unsigned long long c){
    unsigned long long d; asm("fma.rn.f32x2 %0, %1, %2, %3;" : "=l"(d) : "l"(a), "l"(b), "l"(c)); return d;
}
__device__ __forceinline__ void unpack2(unsigned long long v, float& lo, float& hi){
    asm("mov.b64 {%0,%1}, %2;" : "=f"(lo), "=f"(hi) : "l"(v));
}
__device__ __forceinline__ float tanh_fast(float x){
    float y; asm("tanh.approx.f32 %0, %1;" : "=f"(y) : "f"(x)); return y;
}

// ---------------- projection (q and k fused; dead k-rows skipped) ----------------
#define PR 32    // rows per block
#define PT 128   // threads (= Hn)
#define XS 36    // padded smem row stride (floats); 144B, 16B-aligned
#define QBLOCKS ((Bn*Qn)/PR)   // 32
#define KBLOCKS ((Bn*Kn)/PR)   // 512

__global__ __launch_bounds__(PT) void proj_kernel(const float* __restrict__ Xq,
                                                  const float* __restrict__ Wq,
                                                  const float* __restrict__ Xk,
                                                  const float* __restrict__ Wk,
                                                  const int* __restrict__ vlen){
    __shared__ float xs[Dn*XS];   // X tile transposed: xs[d][r]
    const float* X; const float* W; float* out; int row0;
    if (blockIdx.x < QBLOCKS){ X = Xq; W = Wq; out = g_qp; row0 = blockIdx.x * PR; }
    else {
        X = Xk; W = Wk; out = g_kp;
        row0 = (blockIdx.x - QBLOCKS) * PR;
        if ((row0 & (Kn-1)) >= vlen[row0 >> 10]) return;   // dead kp rows
    }
    const int t = threadIdx.x;

    for (int i = t; i < PR*Dn; i += PT){
        int r = i >> 8;          // /256
        int d = i & (Dn-1);
        xs[d*XS + r] = X[(row0 + r)*Dn + d];
    }
    __syncthreads();

    unsigned long long acc[PR/2];
#pragma unroll
    for (int i = 0; i < PR/2; i++) acc[i] = 0ull;

#pragma unroll 2
    for (int d = 0; d < Dn; d++){
        float w = W[d*Hn + t];                       // coalesced, L1-resident
        unsigned long long w2 = pack2(w, w);
        const ulonglong2* xp = reinterpret_cast<const ulonglong2*>(&xs[d*XS]);
#pragma unroll
        for (int m = 0; m < PR/4; m++){
            ulonglong2 xv = xp[m];                   // warp-uniform LDS.128 broadcast
            acc[2*m]   = fma2(w2, xv.x, acc[2*m]);
            acc[2*m+1] = fma2(w2, xv.y, acc[2*m+1]);
        }
    }
#pragma unroll
    for (int i = 0; i < PR/2; i++){
        float lo, hi; unpack2(acc[i], lo, hi);
        out[(row0 + 2*i    )*Hn + t] = lo;
        out[(row0 + 2*i + 1)*Hn + t] = hi;
    }
}

// --------- scores: writes exp(s) where s = sum_h w_v[h]*tanh(qp+kp) ---------
// fp32 MUFU tanh (f16x2 variant tested R11: slower + 100x rel_err — rejected).
// No max subtraction: |s| <= sum|w_v| ~ 9 -> exp in [1e-7, 1e4], exact in fp32.
#define SKT 32
#define SQT 16
#define ST  256

__global__ __launch_bounds__(ST) void score_kernel(const float* __restrict__ wv,
                                                   const int* __restrict__ vlen){
    const int b  = blockIdx.z;
    const int v  = vlen[b];
    const int k0 = blockIdx.x * SKT;
    if (k0 >= v) return;
    const int kmax = min(SKT, v - k0);

    __shared__ float ks[SKT*Hn];     // swizzled kp tile
    __shared__ float qs[SQT*Hn];     // q tile (plain)
    __shared__ float ws[Hn];
    const int t = threadIdx.x;
    if (t < Hn) ws[t] = wv[t];

    const float* kpb = g_kp + (size_t)(b*Kn + k0)*Hn;
    for (int i = t; i < SKT*Hn; i += ST){
        int j = i >> 7, h = i & 127;
        int sidx = j*Hn + ((((h>>2) ^ (j & 7))) << 2) + (h & 3);
        ks[sidx] = kpb[i];
    }
    const int q0 = blockIdx.y * SQT;
    const float* qpb = g_qp + (size_t)(b*Qn + q0)*Hn;
    for (int i = t; i < SQT*Hn; i += ST) qs[i] = qpb[i];
    __syncthreads();

    const int j  = t & 31;        // k lane
    const int qh = t >> 5;        // q phase 0..7 (uniform within warp)
    const int jx = j & 7;
    float* sc = g_attn + (size_t)(b*Qn + q0)*Kn;

#pragma unroll
    for (int qi = 0; qi < SQT/8; qi++){
        const int q = qi*8 + qh;
        float acc0 = 0.f, acc1 = 0.f;
#pragma unroll 8
        for (int c = 0; c < Hn/4; c++){
            float4 kv = *reinterpret_cast<const float4*>(&ks[j*Hn + ((c ^ jx) << 2)]);
            float4 qv = *reinterpret_cast<const float4*>(&qs[q*Hn + (c << 2)]); // broadcast
            float4 w4 = *reinterpret_cast<const float4*>(&ws[c << 2]);
            acc0 += w4.x * tanh_fast(qv.x + kv.x);
            acc1 += w4.y * tanh_fast(qv.y + kv.y);
            acc0 += w4.z * tanh_fast(qv.z + kv.z);
            acc1 += w4.w * tanh_fast(qv.w + kv.w);
        }
        if (j < kmax) sc[q*Kn + k0 + j] = __expf(acc0 + acc1);
    }
}

// --------- out partials + per-split exp sums ---------
#define OQT 16
#define OT  256
#define ASTR 20   // padded attn-tile row stride (floats): 80B, 16B-aligned
#define VB 16     // V load batch

__global__ __launch_bounds__(OT, 4) void outpart_kernel(const float* __restrict__ V,
                                                        const int* __restrict__ vlen){
    const int qt = blockIdx.x;    // 0..3
    const int kz = blockIdx.y;    // 0..KS-1
    const int b  = blockIdx.z;
    const int v  = vlen[b];
    const int k0 = kz * OKS;
    if (k0 >= v) return;                      // dead split: stays zero
    const int q0 = qt * OQT;
    const int t  = threadIdx.x;
    const int kmax = min(OKS, v - k0);

    __shared__ float as[OKS*ASTR];   // e tile: as[k*ASTR + q]
    const float* attb = g_attn + (size_t)(b*Qn + q0)*Kn + k0;
    for (int i = t; i < OQT*OKS; i += OT){
        int q = i >> 6, k = i & (OKS-1);       // lanes: consecutive k, coalesced LDG
        as[k*ASTR + q] = (k < kmax) ? attb[q*Kn + k] : 0.f;
    }
    __syncthreads();

    const int d2 = t & 127;       // d-pair index
    const int qh = t >> 7;        // q-half (warp-uniform)
    const float2* Vt = reinterpret_cast<const float2*>(V + ((size_t)b*Kn + k0)*Dn) + d2;

    unsigned long long accA[4];   // (q2r,q2r+1) x d0 within this half
    unsigned long long accB[4];   // (q2r,q2r+1) x d1
#pragma unroll
    for (int r = 0; r < 4; r++){ accA[r] = 0ull; accB[r] = 0ull; }

#pragma unroll
    for (int gb = 0; gb < OKS/VB; gb++){
        float2 vb[VB];                             // front-batched: MLP=16
#pragma unroll
        for (int i = 0; i < VB; i++) vb[i] = Vt[(size_t)(gb*VB + i)*(Dn/2)];
#pragma unroll
        for (int i = 0; i < VB; i++){
            int k = gb*VB + i;
            unsigned long long v0 = pack2(vb[i].x, vb[i].x);
            unsigned long long v1 = pack2(vb[i].y, vb[i].y);
            const ulonglong2* ap = reinterpret_cast<const ulonglong2*>(&as[k*ASTR]) + 2*qh;
            ulonglong2 a0 = ap[0];    // q = qh*8 + 0..3, broadcast
            ulonglong2 a1 = ap[1];    // q = qh*8 + 4..7
            accA[0] = fma2(a0.x, v0, accA[0]);  accB[0] = fma2(a0.x, v1, accB[0]);
            accA[1] = fma2(a0.y, v0, accA[1]);  accB[1] = fma2(a0.y, v1, accB[1]);
            accA[2] = fma2(a1.x, v0, accA[2]);  accB[2] = fma2(a1.x, v1, accB[2]);
            accA[3] = fma2(a1.y, v0, accA[3]);  accB[3] = fma2(a1.y, v1, accB[3]);
        }
    }

    float* part = g_part + ((size_t)kz*Bn*Qn + b*Qn + q0 + qh*8)*Dn;
#pragma unroll
    for (int r = 0; r < 4; r++){
        float fa, fb, ga, gb2;
        unpack2(accA[r], fa, fb);
        unpack2(accB[r], ga, gb2);
        reinterpret_cast<float2*>(part + (2*r  )*Dn)[d2] = make_float2(fa, ga);
        reinterpret_cast<float2*>(part + (2*r+1)*Dn)[d2] = make_float2(fb, gb2);
    }

    // per-q exp sums of this split (smem unchanged since staging; no sync needed)
    if (t < OQT*8){
        int q = t >> 3, j = t & 7;
        float s = 0.f;
#pragma unroll
        for (int i = 0; i < 8; i++) s += as[(j*8 + i)*ASTR + q];
#pragma unroll
        for (int o = 4; o > 0; o >>= 1) s += __shfl_down_sync(0xffffffffu, s, o, 8);
        if (j == 0) g_psum[kz*(Bn*Qn) + b*Qn + q0 + q] = s;
    }
}

// ------- reduce: out = (1/sum psum) * sum_{live} part -------
// One block per (b,q) row (RI=64 float4 = one row) -> nz is block-uniform,
// z-guards are warp-uniform branches; dead splits are never read.
#define RT 256
#define NOUT4 ((Bn*Qn*Dn)/4)   // 65536 float4
#define RI 64                  // i4 values per block = one (b,q) row

__global__ __launch_bounds__(RT) void reduce_kernel(const int* __restrict__ vlen,
                                                    float* __restrict__ out){
    const int t   = threadIdx.x;
    const int li  = t & (RI-1);
    const int zq  = t >> 6;                   // 0..3 (warp-uniform)
    const int i4  = blockIdx.x * RI + li;
    const int row = blockIdx.x;               // one (b,q) row per block
    const int b   = row >> 6;
    const int nz  = (vlen[b] + OKS - 1) >> 6; // live splits, block-uniform

    const float4* p = reinterpret_cast<const float4*>(g_part);
    float4 x[4];
    float  ps[4];
#pragma unroll
    for (int j = 0; j < 4; j++){              // only live splits touched
        int z = zq*4 + j;
        if (z < nz){
            x[j]  = p[(size_t)z*NOUT4 + i4];
            ps[j] = g_psum[z*(Bn*Qn) + row];
        } else {
            x[j]  = make_float4(0.f, 0.f, 0.f, 0.f);
            ps[j] = 0.f;
        }
    }
    x[0].x += x[1].x; x[0].y += x[1].y; x[0].z += x[1].z; x[0].w += x[1].w;
    x[2].x += x[3].x; x[2].y += x[3].y; x[2].z += x[3].z; x[2].w += x[3].w;
    x[0].x += x[2].x; x[0].y += x[2].y; x[0].z += x[2].z; x[0].w += x[2].w;
    ps[0] += ps[1]; ps[2] += ps[3]; ps[0] += ps[2];

    __shared__ float4 sx[3][RI];
    __shared__ float  sp[3][RI];
    if (zq){ sx[zq-1][li] = x[0]; sp[zq-1][li] = ps[0]; }
    __syncthreads();
    if (zq == 0){
        float4 s = x[0];
        float sm = ps[0];
#pragma unroll
        for (int g = 0; g < 3; g++){
            float4 o = sx[g][li];
            s.x += o.x; s.y += o.y; s.z += o.z; s.w += o.w;
            sm += sp[g][li];
        }
        const float inv = __fdividef(1.f, sm);
        s.x *= inv; s.y *= inv; s.z *= inv; s.w *= inv;
        reinterpret_cast<float4*>(out)[i4] = s;
    }
}

// ---------------- launch ----------------
extern "C" void kernel_launch(void* const* d_in, const int* in_sizes, int n_in,
                              void* d_out, int out_size){
    const float* queries = (const float*)d_in[0];
    const float* keys    = (const float*)d_in[1];
    const float* values  = (const float*)d_in[2];
    const int*   vlen    = (const int*)  d_in[3];
    const float* W_q     = (const float*)d_in[4];
    const float* W_k     = (const float*)d_in[5];
    const float* w_v     = (const float*)d_in[6];
    float* out = (float*)d_out;

    proj_kernel<<<QBLOCKS + KBLOCKS, PT>>>(queries, W_q, keys, W_k, vlen);  // 544 blocks
    score_kernel<<<dim3(Kn/SKT, Qn/SQT, Bn), ST>>>(w_v, vlen);              // 2048 blocks
    outpart_kernel<<<dim3(Qn/OQT, KS, Bn), OT>>>(values, vlen);             // 1024 blocks
    reduce_kernel<<<NOUT4/RI, RT>>>(vlen, out);                             // 1024 blocks
}

// round 13
// speedup vs baseline: 1.1665x; 1.1339x over previous
#include <cuda_runtime.h>

#define Bn 16
#define Qn 64
#define Kn 1024
#define Dn 256
#define Hn 128

// Scratch (device globals: no allocation allowed).
// Zero-initialized at module load; dead splits (k0 >= vlen[b]) are never
// written (vlen constant across replays), so they contribute exact zeros.
__device__ float g_qp[Bn*Qn*Hn];       // projected queries  [B,Q,H]
__device__ float g_kp[Bn*Kn*Hn];       // projected keys     [B,K,H]
#define KS 16
#define OKS (Kn/KS)                    // 64 k per split
__device__ float g_part[KS*Bn*Qn*Dn];  // output partials [KS][B,Q,D]
__device__ float g_psum[KS*Bn*Qn];     // per-split exp row sums [KS][B*Q]

// ---------- packed f32x2 helpers (Blackwell) ----------
__device__ __forceinline__ unsigned long long pack2(float x, float y){
    unsigned long long r; asm("mov.b64 %0, {%1,%2};" : "=l"(r) : "f"(x), "f"(y)); return r;
}
__device__ __forceinline__ unsigned long long fma2(unsigned long long a, unsigned long long b, unsigned long long c){
    unsigned long long d; asm("fma.rn.f32x2 %0, %1, %2, %3;" : "=l"(d) : "l"(a), "l"(b), "l"(c)); return d;
}
__device__ __forceinline__ void unpack2(unsigned long long v, float& lo, float& hi){
    asm("mov.b64 {%0,%1}, %2;" : "=f"(lo), "=f"(hi) : "l"(v));
}
__device__ __forceinline__ float tanh_fast(float x){
    float y; asm("tanh.approx.f32 %0, %1;" : "=f"(y) : "f"(x)); return y;
}

// ---------------- projection (q and k fused; dead k-rows skipped) ----------------
#define PR 32    // rows per block
#define PT 128   // threads (= Hn)
#define XS 36    // padded smem row stride (floats); 144B, 16B-aligned
#define QBLOCKS ((Bn*Qn)/PR)   // 32
#define KBLOCKS ((Bn*Kn)/PR)   // 512

__global__ __launch_bounds__(PT) void proj_kernel(const float* __restrict__ Xq,
                                                  const float* __restrict__ Wq,
                                                  const float* __restrict__ Xk,
                                                  const float* __restrict__ Wk,
                                                  const int* __restrict__ vlen){
    __shared__ float xs[Dn*XS];   // X tile transposed: xs[d][r]
    const float* X; const float* W; float* out; int row0;
    if (blockIdx.x < QBLOCKS){ X = Xq; W = Wq; out = g_qp; row0 = blockIdx.x * PR; }
    else {
        X = Xk; W = Wk; out = g_kp;
        row0 = (blockIdx.x - QBLOCKS) * PR;
        if ((row0 & (Kn-1)) >= vlen[row0 >> 10]) return;   // dead kp rows
    }
    const int t = threadIdx.x;

    for (int i = t; i < PR*Dn; i += PT){
        int r = i >> 8;          // /256
        int d = i & (Dn-1);
        xs[d*XS + r] = X[(row0 + r)*Dn + d];
    }
    __syncthreads();

    unsigned long long acc[PR/2];
#pragma unroll
    for (int i = 0; i < PR/2; i++) acc[i] = 0ull;

#pragma unroll 2
    for (int d = 0; d < Dn; d++){
        float w = W[d*Hn + t];                       // coalesced, L1-resident
        unsigned long long w2 = pack2(w, w);
        const ulonglong2* xp = reinterpret_cast<const ulonglong2*>(&xs[d*XS]);
#pragma unroll
        for (int m = 0; m < PR/4; m++){
            ulonglong2 xv = xp[m];                   // warp-uniform LDS.128 broadcast
            acc[2*m]   = fma2(w2, xv.x, acc[2*m]);
            acc[2*m+1] = fma2(w2, xv.y, acc[2*m+1]);
        }
    }
#pragma unroll
    for (int i = 0; i < PR/2; i++){
        float lo, hi; unpack2(acc[i], lo, hi);
        out[(row0 + 2*i    )*Hn + t] = lo;
        out[(row0 + 2*i + 1)*Hn + t] = hi;
    }
}

// ------- fused score+out: one block = (16q x 64k) tile of one batch -------
// Phase 1: exps of tanh-scores into SMEM (fp32 MUFU tanh; no max shift:
// |s| <= sum|w_v| ~ 9, exp in [1e-7,1e4], exact in fp32).
// Phase 2: V accumulation from SMEM exps -> g_part + g_psum.
// Dead splits (k0 >= v) write NOTHING (stay zero from static init).
#define FQT 16    // q per block
#define FT  256
#define ASTR 20   // padded exp-tile row stride (floats): 80B, 16B-aligned
#define VB 16     // V load batch

__global__ __launch_bounds__(FT) void fused_kernel(const float* __restrict__ V,
                                                   const float* __restrict__ wv,
                                                   const int* __restrict__ vlen){
    const int qt = blockIdx.x;    // 0..3
    const int kz = blockIdx.y;    // 0..KS-1
    const int b  = blockIdx.z;
    const int v  = vlen[b];
    const int k0 = kz * OKS;
    if (k0 >= v) return;                      // dead split
    const int q0 = qt * FQT;
    const int t  = threadIdx.x;
    const int kmax = min(OKS, v - k0);

    __shared__ float ks[OKS*Hn];   // kp tile, swizzled 512B rows (32KB)
    __shared__ float qs[FQT*Hn];   // q tile (8KB)
    __shared__ float ws[Hn];
    __shared__ float es[OKS*ASTR]; // exp tile: es[k*ASTR + q] (5KB)

    if (t < Hn) ws[t] = wv[t];
    const float* kpb = g_kp + (size_t)(b*Kn + k0)*Hn;
    for (int i = t; i < OKS*Hn; i += FT){
        int j = i >> 7, h = i & 127;
        int sidx = j*Hn + ((((h>>2) ^ (j & 7))) << 2) + (h & 3);
        ks[sidx] = kpb[i];
    }
    const float* qpb = g_qp + (size_t)(b*Qn + q0)*Hn;
    for (int i = t; i < FQT*Hn; i += FT) qs[i] = qpb[i];
    __syncthreads();

    // ---- phase 1: scores -> exp in SMEM ----
    {
        const int lane = t & 31;
        const int wrp  = t >> 5;          // 0..7
        const int kh   = wrp & 1;         // k half
        const int qb   = (wrp >> 1) << 2; // q base 0,4,8,12 (warp-uniform)
        const int k    = kh*32 + lane;
        const int jx   = lane & 7;        // swizzle key (= k & 7)

        float a0 = 0.f, a1 = 0.f, a2 = 0.f, a3 = 0.f;
#pragma unroll 8
        for (int c = 0; c < Hn/4; c++){
            float4 kv = *reinterpret_cast<const float4*>(&ks[k*Hn + ((c ^ jx) << 2)]);
            float4 w4 = *reinterpret_cast<const float4*>(&ws[c << 2]);
            float4 q0v = *reinterpret_cast<const float4*>(&qs[(qb  )*Hn + (c << 2)]);
            float4 q1v = *reinterpret_cast<const float4*>(&qs[(qb+1)*Hn + (c << 2)]);
            float4 q2v = *reinterpret_cast<const float4*>(&qs[(qb+2)*Hn + (c << 2)]);
            float4 q3v = *reinterpret_cast<const float4*>(&qs[(qb+3)*Hn + (c << 2)]);
            a0 += w4.x*tanh_fast(q0v.x+kv.x) + w4.y*tanh_fast(q0v.y+kv.y)
                + w4.z*tanh_fast(q0v.z+kv.z) + w4.w*tanh_fast(q0v.w+kv.w);
            a1 += w4.x*tanh_fast(q1v.x+kv.x) + w4.y*tanh_fast(q1v.y+kv.y)
                + w4.z*tanh_fast(q1v.z+kv.z) + w4.w*tanh_fast(q1v.w+kv.w);
            a2 += w4.x*tanh_fast(q2v.x+kv.x) + w4.y*tanh_fast(q2v.y+kv.y)
                + w4.z*tanh_fast(q2v.z+kv.z) + w4.w*tanh_fast(q2v.w+kv.w);
            a3 += w4.x*tanh_fast(q3v.x+kv.x) + w4.y*tanh_fast(q3v.y+kv.y)
                + w4.z*tanh_fast(q3v.z+kv.z) + w4.w*tanh_fast(q3v.w+kv.w);
        }
        const bool live = (k < kmax);
        es[k*ASTR + qb    ] = live ? __expf(a0) : 0.f;
        es[k*ASTR + qb + 1] = live ? __expf(a1) : 0.f;
        es[k*ASTR + qb + 2] = live ? __expf(a2) : 0.f;
        es[k*ASTR + qb + 3] = live ? __expf(a3) : 0.f;
    }
    __syncthreads();

    // ---- phase 2: V accumulation (identical structure to prior outpart) ----
    const int d2 = t & 127;       // d-pair index
    const int qh = t >> 7;        // q-half (warp-uniform)
    const float2* Vt = reinterpret_cast<const float2*>(V + ((size_t)b*Kn + k0)*Dn) + d2;

    unsigned long long accA[4];   // (q2r,q2r+1) x d0 within this half
    unsigned long long accB[4];   // (q2r,q2r+1) x d1
#pragma unroll
    for (int r = 0; r < 4; r++){ accA[r] = 0ull; accB[r] = 0ull; }

#pragma unroll
    for (int gb = 0; gb < OKS/VB; gb++){
        float2 vb[VB];                             // front-batched: MLP=16
#pragma unroll
        for (int i = 0; i < VB; i++) vb[i] = Vt[(size_t)(gb*VB + i)*(Dn/2)];
#pragma unroll
        for (int i = 0; i < VB; i++){
            int k = gb*VB + i;
            unsigned long long v0 = pack2(vb[i].x, vb[i].x);
            unsigned long long v1 = pack2(vb[i].y, vb[i].y);
            const ulonglong2* ap = reinterpret_cast<const ulonglong2*>(&es[k*ASTR]) + 2*qh;
            ulonglong2 a0 = ap[0];    // q = qh*8 + 0..3, broadcast
            ulonglong2 a1 = ap[1];    // q = qh*8 + 4..7
            accA[0] = fma2(a0.x, v0, accA[0]);  accB[0] = fma2(a0.x, v1, accB[0]);
            accA[1] = fma2(a0.y, v0, accA[1]);  accB[1] = fma2(a0.y, v1, accB[1]);
            accA[2] = fma2(a1.x, v0, accA[2]);  accB[2] = fma2(a1.x, v1, accB[2]);
            accA[3] = fma2(a1.y, v0, accA[3]);  accB[3] = fma2(a1.y, v1, accB[3]);
        }
    }

    float* part = g_part + ((size_t)kz*Bn*Qn + b*Qn + q0 + qh*8)*Dn;
#pragma unroll
    for (int r = 0; r < 4; r++){
        float fa, fb, ga, gb2;
        unpack2(accA[r], fa, fb);
        unpack2(accB[r], ga, gb2);
        reinterpret_cast<float2*>(part + (2*r  )*Dn)[d2] = make_float2(fa, ga);
        reinterpret_cast<float2*>(part + (2*r+1)*Dn)[d2] = make_float2(fb, gb2);
    }

    // per-q exp sums of this split (smem unchanged since phase 1; sync done above)
    if (t < FQT*8){
        int q = t >> 3, j = t & 7;
        float s = 0.f;
#pragma unroll
        for (int i = 0; i < 8; i++) s += es[(j*8 + i)*ASTR + q];
#pragma unroll
        for (int o = 4; o > 0; o >>= 1) s += __shfl_down_sync(0xffffffffu, s, o, 8);
        if (j == 0) g_psum[kz*(Bn*Qn) + b*Qn + q0 + q] = s;
    }
}

// ------- reduce: out = (1/sum psum) * sum_{live} part -------
// One block per (b,q) row; nz block-uniform, dead splits never read.
#define RT 256
#define NOUT4 ((Bn*Qn*Dn)/4)   // 65536 float4
#define RI 64                  // i4 values per block = one (b,q) row

__global__ __launch_bounds__(RT) void reduce_kernel(const int* __restrict__ vlen,
                                                    float* __restrict__ out){
    const int t   = threadIdx.x;
    const int li  = t & (RI-1);
    const int zq  = t >> 6;                   // 0..3 (warp-uniform)
    const int i4  = blockIdx.x * RI + li;
    const int row = blockIdx.x;               // one (b,q) row per block
    const int b   = row >> 6;
    const int nz  = (vlen[b] + OKS - 1) >> 6; // live splits, block-uniform

    const float4* p = reinterpret_cast<const float4*>(g_part);
    float4 x[4];
    float  ps[4];
#pragma unroll
    for (int j = 0; j < 4; j++){              // only live splits touched
        int z = zq*4 + j;
        if (z < nz){
            x[j]  = p[(size_t)z*NOUT4 + i4];
            ps[j] = g_psum[z*(Bn*Qn) + row];
        } else {
            x[j]  = make_float4(0.f, 0.f, 0.f, 0.f);
            ps[j] = 0.f;
        }
    }
    x[0].x += x[1].x; x[0].y += x[1].y; x[0].z += x[1].z; x[0].w += x[1].w;
    x[2].x += x[3].x; x[2].y += x[3].y; x[2].z += x[3].z; x[2].w += x[3].w;
    x[0].x += x[2].x; x[0].y += x[2].y; x[0].z += x[2].z; x[0].w += x[2].w;
    ps[0] += ps[1]; ps[2] += ps[3]; ps[0] += ps[2];

    __shared__ float4 sx[3][RI];
    __shared__ float  sp[3][RI];
    if (zq){ sx[zq-1][li] = x[0]; sp[zq-1][li] = ps[0]; }
    __syncthreads();
    if (zq == 0){
        float4 s = x[0];
        float sm = ps[0];
#pragma unroll
        for (int g = 0; g < 3; g++){
            float4 o = sx[g][li];
            s.x += o.x; s.y += o.y; s.z += o.z; s.w += o.w;
            sm += sp[g][li];
        }
        const float inv = __fdividef(1.f, sm);
        s.x *= inv; s.y *= inv; s.z *= inv; s.w *= inv;
        reinterpret_cast<float4*>(out)[i4] = s;
    }
}

// ---------------- launch ----------------
extern "C" void kernel_launch(void* const* d_in, const int* in_sizes, int n_in,
                              void* d_out, int out_size){
    const float* queries = (const float*)d_in[0];
    const float* keys    = (const float*)d_in[1];
    const float* values  = (const float*)d_in[2];
    const int*   vlen    = (const int*)  d_in[3];
    const float* W_q     = (const float*)d_in[4];
    const float* W_k     = (const float*)d_in[5];
    const float* w_v     = (const float*)d_in[6];
    float* out = (float*)d_out;

    proj_kernel<<<QBLOCKS + KBLOCKS, PT>>>(queries, W_q, keys, W_k, vlen);  // 544 blocks
    fused_kernel<<<dim3(Qn/FQT, KS, Bn), FT>>>(values, w_v, vlen);          // 1024 blocks
    reduce_kernel<<<NOUT4/RI, RT>>>(vlen, out);                             // 1024 blocks
}

// round 14
// speedup vs baseline: 1.2058x; 1.0337x over previous
#include <cuda_runtime.h>

#define Bn 16
#define Qn 64
#define Kn 1024
#define Dn 256
#define Hn 128

// Scratch (device globals: no allocation allowed).
// Zero-initialized at module load; dead splits (k0 >= vlen[b]) are never
// written (vlen constant across replays), so they contribute exact zeros.
__device__ float g_qp[Bn*Qn*Hn];       // projected queries  [B,Q,H]
__device__ float g_kp[Bn*Kn*Hn];       // projected keys     [B,K,H]
#define KS 16
#define OKS (Kn/KS)                    // 64 k per split
__device__ float g_part[KS*Bn*Qn*Dn];  // output partials [KS][B,Q,D]
__device__ float g_psum[KS*Bn*Qn];     // per-split exp row sums [KS][B*Q]

// ---------- packed f32x2 helpers (Blackwell) ----------
__device__ __forceinline__ unsigned long long pack2(float x, float y){
    unsigned long long r; asm("mov.b64 %0, {%1,%2};" : "=l"(r) : "f"(x), "f"(y)); return r;
}
__device__ __forceinline__ unsigned long long fma2(unsigned long long a, unsigned long long b, unsigned long long c){
    unsigned long long d; asm("fma.rn.f32x2 %0, %1, %2, %3;" : "=l"(d) : "l"(a), "l"(b), "l"(c)); return d;
}
__device__ __forceinline__ void unpack2(unsigned long long v, float& lo, float& hi){
    asm("mov.b64 {%0,%1}, %2;" : "=f"(lo), "=f"(hi) : "l"(v));
}
__device__ __forceinline__ float tanh_fast(float x){
    float y; asm("tanh.approx.f32 %0, %1;" : "=f"(y) : "f"(x)); return y;
}

// ---------------- projection (q and k fused; dead k-rows skipped) ----------------
// 256 threads: thread owns h = t&127, row-half rh = t>>7 (16 of 32 rows).
// W loads front-batched 8-deep (MLP 8) to cover L2 latency at low occupancy.
#define PR 32    // rows per block
#define PT 256   // threads
#define XS 36    // padded smem row stride (floats); 144B, 16B-aligned
#define WB 8     // W load batch depth
#define QBLOCKS ((Bn*Qn)/PR)   // 32
#define KBLOCKS ((Bn*Kn)/PR)   // 512

__global__ __launch_bounds__(PT) void proj_kernel(const float* __restrict__ Xq,
                                                  const float* __restrict__ Wq,
                                                  const float* __restrict__ Xk,
                                                  const float* __restrict__ Wk,
                                                  const int* __restrict__ vlen){
    __shared__ float xs[Dn*XS];   // X tile transposed: xs[d][r]
    const float* X; const float* W; float* out; int row0;
    if (blockIdx.x < QBLOCKS){ X = Xq; W = Wq; out = g_qp; row0 = blockIdx.x * PR; }
    else {
        X = Xk; W = Wk; out = g_kp;
        row0 = (blockIdx.x - QBLOCKS) * PR;
        if ((row0 & (Kn-1)) >= vlen[row0 >> 10]) return;   // dead kp rows
    }
    const int t = threadIdx.x;

    for (int i = t; i < PR*Dn; i += PT){
        int r = i >> 8;          // /256
        int d = i & (Dn-1);
        xs[d*XS + r] = X[(row0 + r)*Dn + d];
    }
    __syncthreads();

    const int h  = t & 127;      // output column
    const int rh = t >> 7;       // row half (warp-uniform)
    const float* Wh = W + h;

    unsigned long long acc[8];   // 16 rows as 8 f32x2 pairs
#pragma unroll
    for (int i = 0; i < 8; i++) acc[i] = 0ull;

    for (int db = 0; db < Dn; db += WB){
        float wb[WB];                              // front-batched: MLP=8
#pragma unroll
        for (int i = 0; i < WB; i++) wb[i] = Wh[(db + i)*Hn];
#pragma unroll
        for (int i = 0; i < WB; i++){
            unsigned long long w2 = pack2(wb[i], wb[i]);
            const ulonglong2* xp =
                reinterpret_cast<const ulonglong2*>(&xs[(db + i)*XS + rh*16]);
#pragma unroll
            for (int m = 0; m < 4; m++){
                ulonglong2 xv = xp[m];             // warp-uniform LDS.128 broadcast
                acc[2*m]   = fma2(w2, xv.x, acc[2*m]);
                acc[2*m+1] = fma2(w2, xv.y, acc[2*m+1]);
            }
        }
    }
    float* outr = out + (size_t)(row0 + rh*16)*Hn + h;
#pragma unroll
    for (int i = 0; i < 8; i++){
        float lo, hi; unpack2(acc[i], lo, hi);
        outr[(2*i    )*Hn] = lo;
        outr[(2*i + 1)*Hn] = hi;
    }
}

// ------- fused score+out: one block = (16q x 64k) tile of one batch -------
// Phase 1: exps of tanh-scores into SMEM (fp32 MUFU tanh; no max shift:
// |s| <= sum|w_v| ~ 9, exp in [1e-7,1e4], exact in fp32).
// Phase 2: V accumulation from SMEM exps -> g_part + g_psum.
// Dead splits (k0 >= v) write NOTHING (stay zero from static init).
#define FQT 16    // q per block
#define FT  256
#define ASTR 20   // padded exp-tile row stride (floats): 80B, 16B-aligned
#define VB 16     // V load batch

__global__ __launch_bounds__(FT) void fused_kernel(const float* __restrict__ V,
                                                   const float* __restrict__ wv,
                                                   const int* __restrict__ vlen){
    const int qt = blockIdx.x;    // 0..3
    const int kz = blockIdx.y;    // 0..KS-1
    const int b  = blockIdx.z;
    const int v  = vlen[b];
    const int k0 = kz * OKS;
    if (k0 >= v) return;                      // dead split
    const int q0 = qt * FQT;
    const int t  = threadIdx.x;
    const int kmax = min(OKS, v - k0);

    __shared__ float ks[OKS*Hn];   // kp tile, swizzled 512B rows (32KB)
    __shared__ float qs[FQT*Hn];   // q tile (8KB)
    __shared__ float ws[Hn];
    __shared__ float es[OKS*ASTR]; // exp tile: es[k*ASTR + q] (5KB)

    if (t < Hn) ws[t] = wv[t];
    const float* kpb = g_kp + (size_t)(b*Kn + k0)*Hn;
    for (int i = t; i < OKS*Hn; i += FT){
        int j = i >> 7, h = i & 127;
        int sidx = j*Hn + ((((h>>2) ^ (j & 7))) << 2) + (h & 3);
        ks[sidx] = kpb[i];
    }
    const float* qpb = g_qp + (size_t)(b*Qn + q0)*Hn;
    for (int i = t; i < FQT*Hn; i += FT) qs[i] = qpb[i];
    __syncthreads();

    // ---- phase 1: scores -> exp in SMEM ----
    {
        const int lane = t & 31;
        const int wrp  = t >> 5;          // 0..7
        const int kh   = wrp & 1;         // k half
        const int qb   = (wrp >> 1) << 2; // q base 0,4,8,12 (warp-uniform)
        const int k    = kh*32 + lane;
        const int jx   = lane & 7;        // swizzle key (= k & 7)

        float a0 = 0.f, a1 = 0.f, a2 = 0.f, a3 = 0.f;
#pragma unroll 8
        for (int c = 0; c < Hn/4; c++){
            float4 kv = *reinterpret_cast<const float4*>(&ks[k*Hn + ((c ^ jx) << 2)]);
            float4 w4 = *reinterpret_cast<const float4*>(&ws[c << 2]);
            float4 q0v = *reinterpret_cast<const float4*>(&qs[(qb  )*Hn + (c << 2)]);
            float4 q1v = *reinterpret_cast<const float4*>(&qs[(qb+1)*Hn + (c << 2)]);
            float4 q2v = *reinterpret_cast<const float4*>(&qs[(qb+2)*Hn + (c << 2)]);
            float4 q3v = *reinterpret_cast<const float4*>(&qs[(qb+3)*Hn + (c << 2)]);
            a0 += w4.x*tanh_fast(q0v.x+kv.x) + w4.y*tanh_fast(q0v.y+kv.y)
                + w4.z*tanh_fast(q0v.z+kv.z) + w4.w*tanh_fast(q0v.w+kv.w);
            a1 += w4.x*tanh_fast(q1v.x+kv.x) + w4.y*tanh_fast(q1v.y+kv.y)
                + w4.z*tanh_fast(q1v.z+kv.z) + w4.w*tanh_fast(q1v.w+kv.w);
            a2 += w4.x*tanh_fast(q2v.x+kv.x) + w4.y*tanh_fast(q2v.y+kv.y)
                + w4.z*tanh_fast(q2v.z+kv.z) + w4.w*tanh_fast(q2v.w+kv.w);
            a3 += w4.x*tanh_fast(q3v.x+kv.x) + w4.y*tanh_fast(q3v.y+kv.y)
                + w4.z*tanh_fast(q3v.z+kv.z) + w4.w*tanh_fast(q3v.w+kv.w);
        }
        const bool live = (k < kmax);
        es[k*ASTR + qb    ] = live ? __expf(a0) : 0.f;
        es[k*ASTR + qb + 1] = live ? __expf(a1) : 0.f;
        es[k*ASTR + qb + 2] = live ? __expf(a2) : 0.f;
        es[k*ASTR + qb + 3] = live ? __expf(a3) : 0.f;
    }
    __syncthreads();

    // ---- phase 2: V accumulation ----
    const int d2 = t & 127;       // d-pair index
    const int qh = t >> 7;        // q-half (warp-uniform)
    const float2* Vt = reinterpret_cast<const float2*>(V + ((size_t)b*Kn + k0)*Dn) + d2;

    unsigned long long accA[4];   // (q2r,q2r+1) x d0 within this half
    unsigned long long accB[4];   // (q2r,q2r+1) x d1
#pragma unroll
    for (int r = 0; r < 4; r++){ accA[r] = 0ull; accB[r] = 0ull; }

#pragma unroll
    for (int gb = 0; gb < OKS/VB; gb++){
        float2 vb[VB];                             // front-batched: MLP=16
#pragma unroll
        for (int i = 0; i < VB; i++) vb[i] = Vt[(size_t)(gb*VB + i)*(Dn/2)];
#pragma unroll
        for (int i = 0; i < VB; i++){
            int k = gb*VB + i;
            unsigned long long v0 = pack2(vb[i].x, vb[i].x);
            unsigned long long v1 = pack2(vb[i].y, vb[i].y);
            const ulonglong2* ap = reinterpret_cast<const ulonglong2*>(&es[k*ASTR]) + 2*qh;
            ulonglong2 a0 = ap[0];    // q = qh*8 + 0..3, broadcast
            ulonglong2 a1 = ap[1];    // q = qh*8 + 4..7
            accA[0] = fma2(a0.x, v0, accA[0]);  accB[0] = fma2(a0.x, v1, accB[0]);
            accA[1] = fma2(a0.y, v0, accA[1]);  accB[1] = fma2(a0.y, v1, accB[1]);
            accA[2] = fma2(a1.x, v0, accA[2]);  accB[2] = fma2(a1.x, v1, accB[2]);
            accA[3] = fma2(a1.y, v0, accA[3]);  accB[3] = fma2(a1.y, v1, accB[3]);
        }
    }

    float* part = g_part + ((size_t)kz*Bn*Qn + b*Qn + q0 + qh*8)*Dn;
#pragma unroll
    for (int r = 0; r < 4; r++){
        float fa, fb, ga, gb2;
        unpack2(accA[r], fa, fb);
        unpack2(accB[r], ga, gb2);
        reinterpret_cast<float2*>(part + (2*r  )*Dn)[d2] = make_float2(fa, ga);
        reinterpret_cast<float2*>(part + (2*r+1)*Dn)[d2] = make_float2(fb, gb2);
    }

    // per-q exp sums of this split (smem unchanged since phase 1; sync done above)
    if (t < FQT*8){
        int q = t >> 3, j = t & 7;
        float s = 0.f;
#pragma unroll
        for (int i = 0; i < 8; i++) s += es[(j*8 + i)*ASTR + q];
#pragma unroll
        for (int o = 4; o > 0; o >>= 1) s += __shfl_down_sync(0xffffffffu, s, o, 8);
        if (j == 0) g_psum[kz*(Bn*Qn) + b*Qn + q0 + q] = s;
    }
}

// ------- reduce: out = (1/sum psum) * sum_{live} part -------
// One block per (b,q) row; nz block-uniform, dead splits never read.
#define RT 256
#define NOUT4 ((Bn*Qn*Dn)/4)   // 65536 float4
#define RI 64                  // i4 values per block = one (b,q) row

__global__ __launch_bounds__(RT) void reduce_kernel(const int* __restrict__ vlen,
                                                    float* __restrict__ out){
    const int t   = threadIdx.x;
    const int li  = t & (RI-1);
    const int zq  = t >> 6;                   // 0..3 (warp-uniform)
    const int i4  = blockIdx.x * RI + li;
    const int row = blockIdx.x;               // one (b,q) row per block
    const int b   = row >> 6;
    const int nz  = (vlen[b] + OKS - 1) >> 6; // live splits, block-uniform

    const float4* p = reinterpret_cast<const float4*>(g_part);
    float4 x[4];
    float  ps[4];
#pragma unroll
    for (int j = 0; j < 4; j++){              // only live splits touched
        int z = zq*4 + j;
        if (z < nz){
            x[j]  = p[(size_t)z*NOUT4 + i4];
            ps[j] = g_psum[z*(Bn*Qn) + row];
        } else {
            x[j]  = make_float4(0.f, 0.f, 0.f, 0.f);
            ps[j] = 0.f;
        }
    }
    x[0].x += x[1].x; x[0].y += x[1].y; x[0].z += x[1].z; x[0].w += x[1].w;
    x[2].x += x[3].x; x[2].y += x[3].y; x[2].z += x[3].z; x[2].w += x[3].w;
    x[0].x += x[2].x; x[0].y += x[2].y; x[0].z += x[2].z; x[0].w += x[2].w;
    ps[0] += ps[1]; ps[2] += ps[3]; ps[0] += ps[2];

    __shared__ float4 sx[3][RI];
    __shared__ float  sp[3][RI];
    if (zq){ sx[zq-1][li] = x[0]; sp[zq-1][li] = ps[0]; }
    __syncthreads();
    if (zq == 0){
        float4 s = x[0];
        float sm = ps[0];
#pragma unroll
        for (int g = 0; g < 3; g++){
            float4 o = sx[g][li];
            s.x += o.x; s.y += o.y; s.z += o.z; s.w += o.w;
            sm += sp[g][li];
        }
        const float inv = __fdividef(1.f, sm);
        s.x *= inv; s.y *= inv; s.z *= inv; s.w *= inv;
        reinterpret_cast<float4*>(out)[i4] = s;
    }
}

// ---------------- launch ----------------
extern "C" void kernel_launch(void* const* d_in, const int* in_sizes, int n_in,
                              void* d_out, int out_size){
    const float* queries = (const float*)d_in[0];
    const float* keys    = (const float*)d_in[1];
    const float* values  = (const float*)d_in[2];
    const int*   vlen    = (const int*)  d_in[3];
    const float* W_q     = (const float*)d_in[4];
    const float* W_k     = (const float*)d_in[5];
    const float* w_v     = (const float*)d_in[6];
    float* out = (float*)d_out;

    proj_kernel<<<QBLOCKS + KBLOCKS, PT>>>(queries, W_q, keys, W_k, vlen);  // 544 blocks
    fused_kernel<<<dim3(Qn/FQT, KS, Bn), FT>>>(values, w_v, vlen);          // 1024 blocks
    reduce_kernel<<<NOUT4/RI, RT>>>(vlen, out);                             // 1024 blocks
}